// round 14
// baseline (speedup 1.0000x reference)
#include <cuda_runtime.h>
#include <cuda_bf16.h>
#include <cuda_fp16.h>
#include <cstdint>

#define NND 100000
#define NE  1600000
#define KF  256
#define OD  128

// ---------------- device scratch (no allocations allowed) ----------------
__device__ int   g_is64;
__device__ int   g_total;
__device__ int   g_rank[NE];
__device__ int   g_col[NE];
__device__ int   g_srt[NE];
__device__ int   g_deg[NND];
__device__ int   g_start[NND];
__device__ float g_dinv[NND];
__device__ __half g_xh[(size_t)NND * KF];   // x in fp16, 51.2 MB
__device__ __half g_hb[(size_t)NND * OD];   // h = xW+b (unscaled), fp16
__device__ __half g_wt[OD * KF];            // W^T fp16 [n][k]

__device__ __forceinline__ uint32_t smem_u32(const void* p) {
    uint32_t a;
    asm("{ .reg .u64 t; cvta.to.shared.u64 t, %1; cvt.u32.u64 %0, t; }"
        : "=r"(a) : "l"(p));
    return a;
}

#define CP_ASYNC16(dst, src) \
    asm volatile("cp.async.cg.shared.global [%0], [%1], 16;" \
                 :: "r"(dst), "l"(src) : "memory")
#define CP_COMMIT() asm volatile("cp.async.commit_group;" ::: "memory")
#define CP_WAIT0()  asm volatile("cp.async.wait_group 0;" ::: "memory")

// ---------------- launch 1: zero deg + dtype detect + W->fp16 ------------
__global__ void zero_wsplit_kernel(const void* ei, const float* __restrict__ W) {
    int i = blockIdx.x * blockDim.x + threadIdx.x;
    if (i < NND) g_deg[i] = 0;
    if (i == 0) {
        g_total = 0;
        const long long* p = (const long long*)ei;
        int ok64 = 1;
        #pragma unroll
        for (int j = 0; j < 16; j++) {
            long long v = p[j];
            if (v < 0 || v >= NND) ok64 = 0;
        }
        g_is64 = ok64;
    }
    if (i < KF * OD) {
        int k = i >> 7;
        int n = i & 127;
        g_wt[n * KF + k] = __float2half_rn(W[i]);
    }
}

// ---------------- launch 2: x->fp16 stream + degree count (fused) --------
#define CONVX_THREADS (NND * KF / 4)          // 6,400,000
__global__ void convx_deg_kernel(const void* ei, const float* __restrict__ x) {
    int t = blockIdx.x * blockDim.x + threadIdx.x;
    if (t < CONVX_THREADS) {
        float4 v = *(const float4*)(x + (size_t)t * 4);
        __half2 h0 = __floats2half2_rn(v.x, v.y);
        __half2 h1 = __floats2half2_rn(v.z, v.w);
        uint2 o = make_uint2(*(unsigned*)&h0, *(unsigned*)&h1);
        *(uint2*)(g_xh + (size_t)t * 4) = o;
    }
    if (t < NE) {
        int c;
        if (g_is64) c = (int)((const long long*)ei)[t + NE];
        else        c = ((const int*)ei)[t + NE];
        g_col[t] = c;
        g_rank[t] = atomicAdd(&g_deg[c], 1);
    }
}

// ================= launch 3: GEMM (pure fp16 cp.async) ===================
// CTA tile 64(M)x128(N), K chunks of 64. 8 warps 2(M)x4(N), warp 32x32.
static constexpr int SA = 72;
static constexpr int TILE_A = 64 * SA;       // 4608 elems
static constexpr int TILE_B = 128 * SA;      // 9216 elems
static constexpr int SMEM_DYN = (2 * TILE_A + 2 * TILE_B) * 2;   // 55296 B

__device__ __forceinline__ unsigned pack_h2f(float a, float b) {
    __half2 h = __floats2half2_rn(a, b);
    return *(unsigned*)&h;
}

__device__ __forceinline__ void ldmx4(uint32_t addr, uint32_t* r) {
    asm volatile("ldmatrix.sync.aligned.m8n8.x4.shared.b16 {%0,%1,%2,%3}, [%4];"
                 : "=r"(r[0]), "=r"(r[1]), "=r"(r[2]), "=r"(r[3]) : "r"(addr));
}

__device__ __forceinline__ void mma16816h(float* d, const uint32_t* a,
                                          const uint32_t* b) {
    asm volatile(
        "mma.sync.aligned.m16n8k16.row.col.f32.f16.f16.f32 "
        "{%0,%1,%2,%3}, {%4,%5,%6,%7}, {%8,%9}, {%0,%1,%2,%3};"
        : "+f"(d[0]), "+f"(d[1]), "+f"(d[2]), "+f"(d[3])
        : "r"(a[0]), "r"(a[1]), "r"(a[2]), "r"(a[3]), "r"(b[0]), "r"(b[1]));
}

__global__ __launch_bounds__(256) void gemm_mma_kernel(
    const float* __restrict__ bias)
{
    extern __shared__ __half sm[];
    __half* sA[2] = { sm,              sm + TILE_A };
    __half* sB[2] = { sm + 2 * TILE_A, sm + 2 * TILE_A + TILE_B };

    const int tid = threadIdx.x;
    const int wid = tid >> 5;
    const int lane = tid & 31;
    const int wm = wid & 1;
    const int wn = wid >> 1;
    const int rowBase = blockIdx.x * 64;

    float acc[2][4][4];
    #pragma unroll
    for (int i = 0; i < 2; i++)
        #pragma unroll
        for (int j = 0; j < 4; j++)
            #pragma unroll
            for (int q = 0; q < 4; q++) acc[i][j][q] = 0.f;

    const int a_row_off = (lane & 7) + ((lane >> 3) & 1) * 8;
    const int a_col_off = ((lane >> 4) & 1) * 8;
    const int b_n_off   = (lane & 7) + ((lane >> 4) & 1) * 8;
    const int b_k_off   = ((lane >> 3) & 1) * 8;

    auto issue_ab = [&](int k0, int buf) {
        // A: 64 rows x 128B = 512 x 16B chunks; 2 per thread
        uint32_t ab = smem_u32(sA[buf]);
        #pragma unroll
        for (int i = 0; i < 2; i++) {
            int g = tid + i * 256;           // 0..511
            int r = g >> 3;                  // 0..63
            int f8 = g & 7;
            int grow = rowBase + r;
            if (grow < NND) {
                uint32_t doff = (uint32_t)(r * SA + f8 * 8) * 2;
                CP_ASYNC16(ab + doff, g_xh + (size_t)grow * KF + k0 + f8 * 8);
            }
        }
        // B: 128 rows x 128B = 1024 x 16B chunks; 4 per thread
        uint32_t bb = smem_u32(sB[buf]);
        #pragma unroll
        for (int i = 0; i < 4; i++) {
            int g = tid + i * 256;           // 0..1023
            int n = g >> 3;                  // 0..127
            int f8 = g & 7;
            uint32_t doff = (uint32_t)(n * SA + f8 * 8) * 2;
            CP_ASYNC16(bb + doff, g_wt + (size_t)n * KF + k0 + f8 * 8);
        }
        CP_COMMIT();
    };

    issue_ab(0, 0);
    CP_WAIT0();
    __syncthreads();

    for (int c = 0; c < 4; c++) {
        const int buf = c & 1;
        if (c < 3) issue_ab((c + 1) * 64, buf ^ 1);

        const uint32_t a_b = smem_u32(sA[buf]);
        const uint32_t b_b = smem_u32(sB[buf]);

        #pragma unroll
        for (int ks = 0; ks < 4; ks++) {
            const int k = ks * 16;
            uint32_t af[2][4];
            #pragma unroll
            for (int mt = 0; mt < 2; mt++) {
                int row = wm * 32 + mt * 16 + a_row_off;
                uint32_t byoff = (uint32_t)(row * SA + k + a_col_off) * 2;
                ldmx4(a_b + byoff, af[mt]);
            }
            uint32_t bfg[2][4];
            #pragma unroll
            for (int j = 0; j < 2; j++) {
                int n = wn * 32 + j * 16 + b_n_off;
                uint32_t byoff = (uint32_t)(n * SA + k + b_k_off) * 2;
                ldmx4(b_b + byoff, bfg[j]);
            }
            #pragma unroll
            for (int mt = 0; mt < 2; mt++)
                #pragma unroll
                for (int j = 0; j < 2; j++)
                    #pragma unroll
                    for (int h = 0; h < 2; h++)
                        mma16816h(acc[mt][j * 2 + h], af[mt], &bfg[j][h * 2]);
        }

        // wait for the just-issued next buffer before anyone touches it
        CP_WAIT0();
        __syncthreads();
    }

    // ---- epilogue: hb = fp16(acc + bias)  (dinv applied in agg) ----
    const int g4 = lane >> 2;
    const int ti = lane & 3;
    #pragma unroll
    for (int mt = 0; mt < 2; mt++) {
        int r0 = rowBase + wm * 32 + mt * 16 + g4;
        int r1 = r0 + 8;
        #pragma unroll
        for (int nt = 0; nt < 4; nt++) {
            int col = wn * 32 + nt * 8 + ti * 2;
            float b0 = bias[col], b1 = bias[col + 1];
            if (r0 < NND) {
                unsigned v = pack_h2f(acc[mt][nt][0] + b0, acc[mt][nt][1] + b1);
                *(unsigned*)(g_hb + (size_t)r0 * OD + col) = v;
            }
            if (r1 < NND) {
                unsigned v = pack_h2f(acc[mt][nt][2] + b0, acc[mt][nt][3] + b1);
                *(unsigned*)(g_hb + (size_t)r1 * OD + col) = v;
            }
        }
    }
}

// ---------------- launch 4: offsets (warp-aggregated atomic) + dinv ------
__global__ void offset_dinv_kernel() {
    int i = blockIdx.x * blockDim.x + threadIdx.x;
    int lane = threadIdx.x & 31;
    int deg = (i < NND) ? g_deg[i] : 0;
    int s = deg;
    #pragma unroll
    for (int o = 1; o < 32; o <<= 1) {
        int t = __shfl_up_sync(0xffffffffu, s, o);
        if (lane >= o) s += t;
    }
    int total = __shfl_sync(0xffffffffu, s, 31);
    int base = 0;
    if (lane == 0) base = atomicAdd(&g_total, total);
    base = __shfl_sync(0xffffffffu, base, 0);
    if (i < NND) {
        g_start[i] = base + s - deg;
        g_dinv[i] = rsqrtf((float)(deg + 1));
    }
}

// ---------------- launch 5: CSR fill (atomic-free) -----------------------
__global__ void fill_kernel(const void* ei) {
    int e = blockIdx.x * blockDim.x + threadIdx.x;
    if (e >= NE) return;
    int r;
    if (g_is64) r = (int)((const long long*)ei)[e];
    else        r = ((const int*)ei)[e];
    g_srt[g_start[g_col[e]] + g_rank[e]] = r;
}

// ---------------- launch 6: CSR aggregation (warp/node) ------------------
__device__ __forceinline__ float4 h4_to_f4(uint2 v) {
    __half2 a = *(__half2*)&v.x;
    __half2 b = *(__half2*)&v.y;
    float2 fa = __half22float2(a);
    float2 fb = __half22float2(b);
    return make_float4(fa.x, fa.y, fb.x, fb.y);
}

__global__ __launch_bounds__(256) void agg_kernel(float* __restrict__ out) {
    int gid = blockIdx.x * 256 + threadIdx.x;
    int node = gid >> 5;
    if (node >= NND) return;
    int lane = threadIdx.x & 31;
    const __half* hb = g_hb + (size_t)lane * 4;

    float dc = g_dinv[node];
    float4 hc = h4_to_f4(*(const uint2*)(hb + (size_t)node * OD));
    float4 acc = make_float4(hc.x * dc, hc.y * dc, hc.z * dc, hc.w * dc);

    int s = g_start[node];
    int e = s + g_deg[node];
    int i = s;
    for (; i + 4 <= e; i += 4) {
        int r0 = g_srt[i];
        int r1 = g_srt[i + 1];
        int r2 = g_srt[i + 2];
        int r3 = g_srt[i + 3];
        float d0 = g_dinv[r0];
        float d1 = g_dinv[r1];
        float d2 = g_dinv[r2];
        float d3 = g_dinv[r3];
        float4 v0 = h4_to_f4(*(const uint2*)(hb + (size_t)r0 * OD));
        float4 v1 = h4_to_f4(*(const uint2*)(hb + (size_t)r1 * OD));
        float4 v2 = h4_to_f4(*(const uint2*)(hb + (size_t)r2 * OD));
        float4 v3 = h4_to_f4(*(const uint2*)(hb + (size_t)r3 * OD));
        acc.x += v0.x * d0 + v1.x * d1 + v2.x * d2 + v3.x * d3;
        acc.y += v0.y * d0 + v1.y * d1 + v2.y * d2 + v3.y * d3;
        acc.z += v0.z * d0 + v1.z * d1 + v2.z * d2 + v3.z * d3;
        acc.w += v0.w * d0 + v1.w * d1 + v2.w * d2 + v3.w * d3;
    }
    for (; i < e; i++) {
        int r0 = g_srt[i];
        float d0 = g_dinv[r0];
        float4 v0 = h4_to_f4(*(const uint2*)(hb + (size_t)r0 * OD));
        acc.x += v0.x * d0;
        acc.y += v0.y * d0;
        acc.z += v0.z * d0;
        acc.w += v0.w * d0;
    }

    float4 o;
    o.x = fmaxf(acc.x * dc, 0.f);
    o.y = fmaxf(acc.y * dc, 0.f);
    o.z = fmaxf(acc.z * dc, 0.f);
    o.w = fmaxf(acc.w * dc, 0.f);
    *(float4*)(out + (size_t)node * OD + lane * 4) = o;
}

// ---------------- launch ----------------
extern "C" void kernel_launch(void* const* d_in, const int* in_sizes, int n_in,
                              void* d_out, int out_size) {
    const float* x  = (const float*)d_in[0];
    const void*  ei = d_in[1];
    const float* W  = (const float*)d_in[2];
    const float* b  = (const float*)d_in[3];
    float* out = (float*)d_out;

    cudaFuncSetAttribute(gemm_mma_kernel,
                         cudaFuncAttributeMaxDynamicSharedMemorySize, SMEM_DYN);

    zero_wsplit_kernel<<<(NND + 255) / 256, 256>>>(ei, W);
    convx_deg_kernel<<<(CONVX_THREADS + 255) / 256, 256>>>(ei, x);
    gemm_mma_kernel<<<(NND + 63) / 64, 256, SMEM_DYN>>>(b);
    offset_dinv_kernel<<<(NND + 255) / 256, 256>>>();
    fill_kernel<<<(NE + 255) / 256, 256>>>(ei);
    agg_kernel<<<(NND * 32 + 255) / 256, 256>>>(out);
}

// round 15
// speedup vs baseline: 1.2023x; 1.2023x over previous
#include <cuda_runtime.h>
#include <cuda_bf16.h>
#include <cuda_fp16.h>
#include <cstdint>

#define NND 100000
#define NE  1600000
#define KF  256
#define OD  128

// ---------------- device scratch (no allocations allowed) ----------------
__device__ int   g_is64;
__device__ int   g_total;
__device__ int   g_rank[NE];
__device__ int   g_col[NE];
__device__ int   g_srt[NE];
__device__ int   g_deg[NND];
__device__ int   g_start[NND];
__device__ float g_dinv[NND];
__device__ __half g_hb[(size_t)NND * OD];   // h = dinv*(xW+b), fp16
__device__ __half g_wt[OD * KF];            // W^T fp16 [n][k]

__device__ __forceinline__ uint32_t smem_u32(const void* p) {
    uint32_t a;
    asm("{ .reg .u64 t; cvta.to.shared.u64 t, %1; cvt.u32.u64 %0, t; }"
        : "=r"(a) : "l"(p));
    return a;
}

#define CP_ASYNC16(dst, src) \
    asm volatile("cp.async.cg.shared.global [%0], [%1], 16;" \
                 :: "r"(dst), "l"(src) : "memory")
#define CP_COMMIT() asm volatile("cp.async.commit_group;" ::: "memory")
#define CP_WAIT0()  asm volatile("cp.async.wait_group 0;" ::: "memory")

// ---------------- launch 1: zero deg + dtype detect + W->fp16 ------------
__global__ void zero_wsplit_kernel(const void* ei, const float* __restrict__ W) {
    int i = blockIdx.x * blockDim.x + threadIdx.x;
    if (i < NND) g_deg[i] = 0;
    if (i == 0) {
        g_total = 0;
        const long long* p = (const long long*)ei;
        int ok64 = 1;
        #pragma unroll
        for (int j = 0; j < 16; j++) {
            long long v = p[j];
            if (v < 0 || v >= NND) ok64 = 0;
        }
        g_is64 = ok64;
    }
    if (i < KF * OD) {
        int k = i >> 7;
        int n = i & 127;
        g_wt[n * KF + k] = __float2half_rn(W[i]);
    }
}

// ---------------- launch 2: degree count + rank + col cache --------------
__global__ void conv_deg_kernel(const void* ei) {
    int e = blockIdx.x * blockDim.x + threadIdx.x;
    if (e >= NE) return;
    int c;
    if (g_is64) c = (int)((const long long*)ei)[e + NE];
    else        c = ((const int*)ei)[e + NE];
    g_col[e] = c;
    g_rank[e] = atomicAdd(&g_deg[c], 1);
}

// ---------------- launch 3: offsets (warp-aggregated atomic) + dinv ------
__global__ void offset_dinv_kernel() {
    int i = blockIdx.x * blockDim.x + threadIdx.x;
    int lane = threadIdx.x & 31;
    int deg = (i < NND) ? g_deg[i] : 0;
    int s = deg;
    #pragma unroll
    for (int o = 1; o < 32; o <<= 1) {
        int t = __shfl_up_sync(0xffffffffu, s, o);
        if (lane >= o) s += t;
    }
    int total = __shfl_sync(0xffffffffu, s, 31);
    int base = 0;
    if (lane == 0) base = atomicAdd(&g_total, total);
    base = __shfl_sync(0xffffffffu, base, 0);
    if (i < NND) {
        g_start[i] = base + s - deg;
        g_dinv[i] = rsqrtf((float)(deg + 1));
    }
}

// ================= launch 4: GEMM (mma.sync fp16, exactly R11) ===========
// CTA tile 64(M)x128(N), K chunks of 64. 8 warps 2(M)x4(N), warp 32x32.
static constexpr int SA = 72;
static constexpr int TILE_A = 64 * SA;
static constexpr int TILE_B = 128 * SA;
static constexpr int SMEM_DYN = (2 * TILE_A + 2 * TILE_B) * 2;   // 55296 B

__device__ __forceinline__ unsigned pack_h2f(float a, float b) {
    __half2 h = __floats2half2_rn(a, b);
    return *(unsigned*)&h;
}

__device__ __forceinline__ void ldmx4(uint32_t addr, uint32_t* r) {
    asm volatile("ldmatrix.sync.aligned.m8n8.x4.shared.b16 {%0,%1,%2,%3}, [%4];"
                 : "=r"(r[0]), "=r"(r[1]), "=r"(r[2]), "=r"(r[3]) : "r"(addr));
}

__device__ __forceinline__ void mma16816h(float* d, const uint32_t* a,
                                          const uint32_t* b) {
    asm volatile(
        "mma.sync.aligned.m16n8k16.row.col.f32.f16.f16.f32 "
        "{%0,%1,%2,%3}, {%4,%5,%6,%7}, {%8,%9}, {%0,%1,%2,%3};"
        : "+f"(d[0]), "+f"(d[1]), "+f"(d[2]), "+f"(d[3])
        : "r"(a[0]), "r"(a[1]), "r"(a[2]), "r"(a[3]), "r"(b[0]), "r"(b[1]));
}

__global__ __launch_bounds__(256) void gemm_mma_kernel(
    const float* __restrict__ x, const float* __restrict__ bias)
{
    extern __shared__ __half sm[];
    __half* sA[2] = { sm,              sm + TILE_A };
    __half* sB[2] = { sm + 2 * TILE_A, sm + 2 * TILE_A + TILE_B };

    const int tid = threadIdx.x;
    const int wid = tid >> 5;
    const int lane = tid & 31;
    const int wm = wid & 1;
    const int wn = wid >> 1;
    const int rowBase = blockIdx.x * 64;

    float acc[2][4][4];
    #pragma unroll
    for (int i = 0; i < 2; i++)
        #pragma unroll
        for (int j = 0; j < 4; j++)
            #pragma unroll
            for (int q = 0; q < 4; q++) acc[i][j][q] = 0.f;

    const int a_row_off = (lane & 7) + ((lane >> 3) & 1) * 8;
    const int a_col_off = ((lane >> 4) & 1) * 8;
    const int b_n_off   = (lane & 7) + ((lane >> 4) & 1) * 8;
    const int b_k_off   = ((lane >> 3) & 1) * 8;

    float4 areg[4];

    auto load_a = [&](int k0) {
        #pragma unroll
        for (int i = 0; i < 4; i++) {
            int g = tid + i * 256;
            int r = g >> 4;
            int f4 = g & 15;
            int grow = rowBase + r;
            areg[i] = make_float4(0.f, 0.f, 0.f, 0.f);
            if (grow < NND)
                areg[i] = *(const float4*)(x + (size_t)grow * KF + k0 + f4 * 4);
        }
    };
    auto store_a = [&](int buf) {
        #pragma unroll
        for (int i = 0; i < 4; i++) {
            int g = tid + i * 256;
            int r = g >> 4;
            int f4 = g & 15;
            float4 v = areg[i];
            int off = r * SA + f4 * 4;
            *(uint2*)(sA[buf] + off) =
                make_uint2(pack_h2f(v.x, v.y), pack_h2f(v.z, v.w));
        }
    };
    auto issue_b = [&](int k0, int buf) {
        uint32_t bb = smem_u32(sB[buf]);
        #pragma unroll
        for (int i = 0; i < 4; i++) {
            int g = tid + i * 256;
            int n = g >> 3;
            int f8 = g & 7;
            uint32_t doff = (uint32_t)(n * SA + f8 * 8) * 2;
            CP_ASYNC16(bb + doff, g_wt + (size_t)n * KF + k0 + f8 * 8);
        }
        CP_COMMIT();
    };

    load_a(0);
    issue_b(0, 0);
    store_a(0);
    CP_WAIT0();
    __syncthreads();

    for (int c = 0; c < 4; c++) {
        const int buf = c & 1;
        if (c < 3) {
            issue_b((c + 1) * 64, buf ^ 1);
            load_a((c + 1) * 64);
        }

        const uint32_t a_b = smem_u32(sA[buf]);
        const uint32_t b_b = smem_u32(sB[buf]);

        #pragma unroll
        for (int ks = 0; ks < 4; ks++) {
            const int k = ks * 16;
            uint32_t af[2][4];
            #pragma unroll
            for (int mt = 0; mt < 2; mt++) {
                int row = wm * 32 + mt * 16 + a_row_off;
                uint32_t byoff = (uint32_t)(row * SA + k + a_col_off) * 2;
                ldmx4(a_b + byoff, af[mt]);
            }
            uint32_t bfg[2][4];
            #pragma unroll
            for (int j = 0; j < 2; j++) {
                int n = wn * 32 + j * 16 + b_n_off;
                uint32_t byoff = (uint32_t)(n * SA + k + b_k_off) * 2;
                ldmx4(b_b + byoff, bfg[j]);
            }
            #pragma unroll
            for (int mt = 0; mt < 2; mt++)
                #pragma unroll
                for (int j = 0; j < 2; j++)
                    #pragma unroll
                    for (int h = 0; h < 2; h++)
                        mma16816h(acc[mt][j * 2 + h], af[mt], &bfg[j][h * 2]);
        }

        if (c < 3) {
            store_a(buf ^ 1);
            CP_WAIT0();
        }
        __syncthreads();
    }

    // ---- epilogue: hb = fp16( dinv[row] * (acc + bias) ) ----
    const int g4 = lane >> 2;
    const int ti = lane & 3;
    #pragma unroll
    for (int mt = 0; mt < 2; mt++) {
        int r0 = rowBase + wm * 32 + mt * 16 + g4;
        int r1 = r0 + 8;
        float d0 = (r0 < NND) ? g_dinv[r0] : 0.f;
        float d1 = (r1 < NND) ? g_dinv[r1] : 0.f;
        #pragma unroll
        for (int nt = 0; nt < 4; nt++) {
            int col = wn * 32 + nt * 8 + ti * 2;
            float b0 = bias[col], b1 = bias[col + 1];
            if (r0 < NND) {
                unsigned v = pack_h2f((acc[mt][nt][0] + b0) * d0,
                                      (acc[mt][nt][1] + b1) * d0);
                *(unsigned*)(g_hb + (size_t)r0 * OD + col) = v;
            }
            if (r1 < NND) {
                unsigned v = pack_h2f((acc[mt][nt][2] + b0) * d1,
                                      (acc[mt][nt][3] + b1) * d1);
                *(unsigned*)(g_hb + (size_t)r1 * OD + col) = v;
            }
        }
    }
}

// ---------------- launch 5: CSR fill (atomic-free, row-half only) --------
__global__ void fill_kernel(const void* ei) {
    int e = blockIdx.x * blockDim.x + threadIdx.x;
    if (e >= NE) return;
    int r;
    if (g_is64) r = (int)((const long long*)ei)[e];
    else        r = ((const int*)ei)[e];
    g_srt[g_start[g_col[e]] + g_rank[e]] = r;
}

// ---------------- launch 6: CSR aggregation (warp/node, unroll 8) --------
__device__ __forceinline__ float4 h4_to_f4(uint2 v) {
    __half2 a = *(__half2*)&v.x;
    __half2 b = *(__half2*)&v.y;
    float2 fa = __half22float2(a);
    float2 fb = __half22float2(b);
    return make_float4(fa.x, fa.y, fb.x, fb.y);
}

__global__ __launch_bounds__(256) void agg_kernel(float* __restrict__ out) {
    int gid = blockIdx.x * 256 + threadIdx.x;
    int node = gid >> 5;
    if (node >= NND) return;
    int lane = threadIdx.x & 31;
    const __half* hb = g_hb + (size_t)lane * 4;

    // self-loop: hb already includes dinv[node]
    float4 acc = h4_to_f4(*(const uint2*)(hb + (size_t)node * OD));

    int s = g_start[node];
    int e = s + g_deg[node];
    int i = s;
    for (; i + 8 <= e; i += 8) {
        int rr[8];
        #pragma unroll
        for (int u = 0; u < 8; u++) rr[u] = g_srt[i + u];
        uint2 uu[8];
        #pragma unroll
        for (int u = 0; u < 8; u++)
            uu[u] = *(const uint2*)(hb + (size_t)rr[u] * OD);
        #pragma unroll
        for (int u = 0; u < 8; u++) {
            float4 v = h4_to_f4(uu[u]);
            acc.x += v.x; acc.y += v.y; acc.z += v.z; acc.w += v.w;
        }
    }
    for (; i < e; i++) {
        int r0 = g_srt[i];
        float4 v0 = h4_to_f4(*(const uint2*)(hb + (size_t)r0 * OD));
        acc.x += v0.x; acc.y += v0.y; acc.z += v0.z; acc.w += v0.w;
    }

    float d = g_dinv[node];
    float4 o;
    o.x = fmaxf(acc.x * d, 0.f);
    o.y = fmaxf(acc.y * d, 0.f);
    o.z = fmaxf(acc.z * d, 0.f);
    o.w = fmaxf(acc.w * d, 0.f);
    *(float4*)(out + (size_t)node * OD + lane * 4) = o;
}

// ---------------- launch ----------------
extern "C" void kernel_launch(void* const* d_in, const int* in_sizes, int n_in,
                              void* d_out, int out_size) {
    const float* x  = (const float*)d_in[0];
    const void*  ei = d_in[1];
    const float* W  = (const float*)d_in[2];
    const float* b  = (const float*)d_in[3];
    float* out = (float*)d_out;

    cudaFuncSetAttribute(gemm_mma_kernel,
                         cudaFuncAttributeMaxDynamicSharedMemorySize, SMEM_DYN);

    zero_wsplit_kernel<<<(NND + 255) / 256, 256>>>(ei, W);
    conv_deg_kernel<<<(NE + 255) / 256, 256>>>(ei);
    offset_dinv_kernel<<<(NND + 255) / 256, 256>>>();
    gemm_mma_kernel<<<(NND + 63) / 64, 256, SMEM_DYN>>>(x, b);
    fill_kernel<<<(NE + 255) / 256, 256>>>(ei);
    agg_kernel<<<(NND * 32 + 255) / 256, 256>>>(out);
}